// round 1
// baseline (speedup 1.0000x reference)
#include <cuda_runtime.h>

#define NUM_SEG   32
#define MUL       128
#define D         3
#define NUM_PATHS 64
#define SEG_ELEMS (MUL * D)              // 384 floats per segment
#define ROW_ELEMS (NUM_SEG * SEG_ELEMS)  // 12288 floats per batch row

// Dynamic smem layout:
//   acc  [12288] floats  (48 KB)  per-b output accumulator
//   M    [64*9]  floats           per-path 3x3 matrices (i*3+k)
//   s0s  [64]    ints             idx0[p] * SEG_ELEMS
//   s2s  [64]    ints             idx2[p] * SEG_ELEMS
#define SMEM_FLOATS (ROW_ELEMS + NUM_PATHS * 9)
#define SMEM_BYTES  (SMEM_FLOATS * 4 + NUM_PATHS * 2 * 4)

__global__ __launch_bounds__(128, 4)
void ftp3_kernel(const float* __restrict__ x0,
                 const float* __restrict__ x1,
                 const float* __restrict__ coeff,
                 const int*   __restrict__ idx0,
                 const int*   __restrict__ idx1,
                 const int*   __restrict__ idx2,
                 float*       __restrict__ out)
{
    extern __shared__ float smem[];
    float* acc = smem;                         // 12288 floats
    float* M   = smem + ROW_ELEMS;             // 576 floats
    int*   s0s = (int*)(M + NUM_PATHS * 9);    // 64 ints
    int*   s2s = s0s + NUM_PATHS;              // 64 ints

    const int t = threadIdx.x;       // 0..127, one u per thread
    const int b = blockIdx.x;        // one batch element per CTA
    const float* x0b = x0 + (size_t)b * ROW_ELEMS;

    // Zero the accumulator with 128-bit stores.
    float4* acc4 = (float4*)acc;
    #pragma unroll
    for (int j = t; j < ROW_ELEMS / 4; j += 128)
        acc4[j] = make_float4(0.f, 0.f, 0.f, 0.f);

    // Threads 0..63 each build one path's 3x3 matrix M[p][i][k]
    //   M = sum_j x1[b, idx1[p], j] * coeff[p, i, j, k]
    if (t < NUM_PATHS) {
        const int p = t;
        s0s[p] = idx0[p] * SEG_ELEMS;
        s2s[p] = idx2[p] * SEG_ELEMS;
        const float* c   = coeff + p * 27;                      // [i][j][k]
        const float* x1b = x1 + (size_t)b * (NUM_SEG * D) + idx1[p] * D;
        const float j0 = x1b[0], j1 = x1b[1], j2 = x1b[2];
        #pragma unroll
        for (int i = 0; i < 3; ++i) {
            #pragma unroll
            for (int k = 0; k < 3; ++k) {
                M[p * 9 + i * 3 + k] =
                    j0 * c[i * 9 + 0 * 3 + k] +
                    j1 * c[i * 9 + 1 * 3 + k] +
                    j2 * c[i * 9 + 2 * 3 + k];
            }
        }
    }
    __syncthreads();

    // Path loop: thread t owns output element (u=t, k=0..2) of whichever
    // segment idx2[p] selects -> no cross-thread races, no syncs needed.
    const int u3 = t * 3;
    #pragma unroll 4
    for (int p = 0; p < NUM_PATHS; ++p) {
        const float* xs = x0b + s0s[p] + u3;
        const float a0 = xs[0];
        const float a1 = xs[1];
        const float a2 = xs[2];
        const float* m = M + p * 9;
        float* ap = acc + s2s[p] + u3;
        ap[0] += a0 * m[0] + a1 * m[3] + a2 * m[6];
        ap[1] += a0 * m[1] + a1 * m[4] + a2 * m[7];
        ap[2] += a0 * m[2] + a1 * m[5] + a2 * m[8];
    }
    __syncthreads();

    // Stream the finished 48 KB row to GMEM with 128-bit stores.
    float4* ob4 = (float4*)(out + (size_t)b * ROW_ELEMS);
    #pragma unroll
    for (int j = t; j < ROW_ELEMS / 4; j += 128)
        ob4[j] = acc4[j];
}

extern "C" void kernel_launch(void* const* d_in, const int* in_sizes, int n_in,
                              void* d_out, int out_size)
{
    const float* x0    = (const float*)d_in[0];  // (2048, 12288)
    const float* x1    = (const float*)d_in[1];  // (2048, 96)
    const float* coeff = (const float*)d_in[2];  // (64, 27)
    const int*   idx0  = (const int*)d_in[3];
    const int*   idx1  = (const int*)d_in[4];
    const int*   idx2  = (const int*)d_in[5];
    float*       out   = (float*)d_out;          // (2048, 12288)

    const int batch = in_sizes[0] / ROW_ELEMS;   // 2048

    cudaFuncSetAttribute(ftp3_kernel,
                         cudaFuncAttributeMaxDynamicSharedMemorySize,
                         SMEM_BYTES);

    ftp3_kernel<<<batch, 128, SMEM_BYTES>>>(x0, x1, coeff, idx0, idx1, idx2, out);
}

// round 3
// speedup vs baseline: 2.0798x; 2.0798x over previous
#include <cuda_runtime.h>

#define NUM_SEG   32
#define MUL       128
#define D         3
#define NUM_PATHS 64
#define SEG_ELEMS (MUL * D)              // 384 floats per segment
#define ROW_ELEMS (NUM_SEG * SEG_ELEMS)  // 12288 floats per batch row

// Path schedule computed once per launch by setup_kernel (deterministic,
// graph-capturable, no allocation: __device__ globals).
__device__ int g_order[NUM_PATHS];       // paths sorted by idx2
__device__ int g_off0[NUM_PATHS];        // idx0[order[q]] * SEG_ELEMS
__device__ int g_segptr[NUM_SEG + 1];    // CSR offsets into g_order per segment

__global__ void ftp3_setup(const int* __restrict__ idx0,
                           const int* __restrict__ idx2)
{
    // 64 elements: trivial serial counting sort on one thread.
    if (threadIdx.x != 0 || blockIdx.x != 0) return;
    int cnt[NUM_SEG];
    #pragma unroll
    for (int s = 0; s < NUM_SEG; ++s) cnt[s] = 0;
    for (int p = 0; p < NUM_PATHS; ++p) cnt[idx2[p]]++;
    int ptr = 0;
    for (int s = 0; s < NUM_SEG; ++s) {
        g_segptr[s] = ptr;
        int c = cnt[s];
        cnt[s] = ptr;        // reuse as write cursor
        ptr += c;
    }
    g_segptr[NUM_SEG] = ptr;
    for (int p = 0; p < NUM_PATHS; ++p) {
        int q = cnt[idx2[p]]++;
        g_order[q] = p;
        g_off0[q]  = idx0[p] * SEG_ELEMS;
    }
}

__global__ __launch_bounds__(128)
void ftp3_main(const float* __restrict__ x0,
               const float* __restrict__ x1,
               const float* __restrict__ coeff,
               const int*   __restrict__ idx1,
               float*       __restrict__ out)
{
    __shared__ float M[NUM_PATHS * 9];        // per-path 3x3 matrices
    __shared__ int   s_moff[NUM_PATHS];       // order[q]*9
    __shared__ int   s_off0[NUM_PATHS];       // idx0 offset per sorted path
    __shared__ int   s_ptr[NUM_SEG + 1];

    const int t = threadIdx.x;                // 0..127, one u per thread
    const int b = blockIdx.x;                 // one batch row per CTA

    if (t < NUM_PATHS) {
        s_moff[t] = g_order[t] * 9;
        s_off0[t] = g_off0[t];
    }
    if (t >= NUM_PATHS && t < NUM_PATHS + NUM_SEG + 1)
        s_ptr[t - NUM_PATHS] = g_segptr[t - NUM_PATHS];

    // Threads 0..63: build M[p][i][k] = sum_j x1[b, idx1[p], j] * coeff[p,i,j,k]
    if (t < NUM_PATHS) {
        const int p = t;
        const float* c   = coeff + p * 27;                         // [i][j][k]
        const float* x1b = x1 + (size_t)b * (NUM_SEG * D) + idx1[p] * D;
        const float j0 = x1b[0], j1 = x1b[1], j2 = x1b[2];
        #pragma unroll
        for (int i = 0; i < 3; ++i)
            #pragma unroll
            for (int k = 0; k < 3; ++k)
                M[p * 9 + i * 3 + k] =
                    j0 * c[i * 9 + 0 * 3 + k] +
                    j1 * c[i * 9 + 1 * 3 + k] +
                    j2 * c[i * 9 + 2 * 3 + k];
    }
    __syncthreads();

    const float* x0b  = x0  + (size_t)b * ROW_ELEMS;
    float*       outb = out + (size_t)b * ROW_ELEMS;
    const int u3 = t * 3;

    // Segments in order: accumulate this segment's paths in registers,
    // then write straight to GMEM. Segments with no paths emit zeros.
    for (int s = 0; s < NUM_SEG; ++s) {
        float f0 = 0.f, f1 = 0.f, f2 = 0.f;
        const int qe = s_ptr[s + 1];
        for (int q = s_ptr[s]; q < qe; ++q) {
            const float* xs = x0b + s_off0[q] + u3;
            const float a0 = xs[0];
            const float a1 = xs[1];
            const float a2 = xs[2];
            const float* m = M + s_moff[q];
            f0 += a0 * m[0] + a1 * m[3] + a2 * m[6];
            f1 += a0 * m[1] + a1 * m[4] + a2 * m[7];
            f2 += a0 * m[2] + a1 * m[5] + a2 * m[8];
        }
        float* o = outb + s * SEG_ELEMS + u3;
        o[0] = f0;
        o[1] = f1;
        o[2] = f2;
    }
}

extern "C" void kernel_launch(void* const* d_in, const int* in_sizes, int n_in,
                              void* d_out, int out_size)
{
    const float* x0    = (const float*)d_in[0];  // (2048, 12288)
    const float* x1    = (const float*)d_in[1];  // (2048, 96)
    const float* coeff = (const float*)d_in[2];  // (64, 27)
    const int*   idx0  = (const int*)d_in[3];
    const int*   idx1  = (const int*)d_in[4];
    const int*   idx2  = (const int*)d_in[5];
    float*       out   = (float*)d_out;          // (2048, 12288)

    const int batch = in_sizes[0] / ROW_ELEMS;   // 2048

    ftp3_setup<<<1, 32>>>(idx0, idx2);
    ftp3_main<<<batch, 128>>>(x0, x1, coeff, idx1, out);
}